// round 4
// baseline (speedup 1.0000x reference)
#include <cuda_runtime.h>
#include <cstdint>

constexpr int NTR  = 4096;
constexpr int NTE  = 2048;
constexpr int NTE2 = 2176;          // NTE + 128 (y folded in as col 2048)
constexpr int DIM  = 16;
constexpr int BS   = 128;
constexpr int NB   = NTR / BS;      // 32

// ---- scratch (device globals; no runtime allocation) ----
__device__ float g_L [(size_t)NTR * NTR];    // Knn -> L (lower)
__device__ float g_Ks[(size_t)NTR * NTE2];   // [Kstar | y | 0-pad]  (stays intact)
__device__ float g_V [(size_t)NTR * NTE2];   // copy of Ks, solved in place -> V
__device__ float g_invD[NB * BS * BS];       // inverses of diag L blocks
__device__ float g_xs[NTR * DIM];
__device__ float g_ts[NTE * DIM];
__device__ float g_sqx[NTR];
__device__ float g_sqt[NTE];
__device__ float g_b[NTR];
__device__ float g_alpha[NTR];
__device__ float g_partM[8 * NTE];
__device__ float g_partV[8 * NTE];
__device__ float g_params[2];                // sigmaf2, sigman2
__device__ float g_scale[DIM];

// ---------------------------------------------------------------- prep
__global__ void k_prep(const float* lsf2, const float* ll2, const float* lsn2) {
    int t = threadIdx.x;
    if (t == 0) { g_params[0] = expf(lsf2[0]); g_params[1] = expf(lsn2[0]); }
    if (t < DIM) g_scale[t] = sqrtf(0.5f * expf(-ll2[t]));
}

__global__ void k_scale(const float* __restrict__ in, float* __restrict__ out,
                        float* __restrict__ sq, int n) {
    int i = blockIdx.x * blockDim.x + threadIdx.x;
    if (i >= n) return;
    float s = 0.f;
#pragma unroll
    for (int d = 0; d < DIM; d++) {
        float v = in[i * DIM + d] * g_scale[d];
        out[i * DIM + d] = v;
        s += v * v;
    }
    sq[i] = s;
}

// ------------------------------------------------------- kernel builders
__global__ void k_build_knn() {
    __shared__ float A[32][DIM];
    __shared__ float B[32][DIM + 1];
    int bi = blockIdx.y * 32, bj = blockIdx.x * 32;
    int t = threadIdx.x;
    for (int idx = t; idx < 32 * DIM; idx += 256) {
        int r = idx / DIM, d = idx % DIM;
        A[r][d] = g_xs[(bi + r) * DIM + d];
        B[r][d] = g_xs[(bj + r) * DIM + d];
    }
    __syncthreads();
    float sf2 = g_params[0], sn2 = g_params[1];
    int tx = t & 31, ty = t >> 5;
    int j = bj + tx;
    float sqj = g_sqx[j];
#pragma unroll
    for (int q = 0; q < 4; q++) {
        int li = ty * 4 + q, i = bi + li;
        float dot = 0.f;
#pragma unroll
        for (int d = 0; d < DIM; d++) dot += A[li][d] * B[tx][d];
        float d2 = fmaxf(g_sqx[i] + sqj - 2.f * dot, 0.f);
        float v = sf2 * expf(-d2);
        if (i == j) v += sn2;
        g_L[(size_t)i * NTR + j] = v;
    }
}

__global__ void k_build_ks() {
    __shared__ float A[32][DIM];
    __shared__ float B[32][DIM + 1];
    int bi = blockIdx.y * 32, bj = blockIdx.x * 32;
    int t = threadIdx.x;
    for (int idx = t; idx < 32 * DIM; idx += 256) {
        int r = idx / DIM, d = idx % DIM;
        A[r][d] = g_xs[(bi + r) * DIM + d];
        B[r][d] = g_ts[(bj + r) * DIM + d];
    }
    __syncthreads();
    float sf2 = g_params[0];
    int tx = t & 31, ty = t >> 5;
    int j = bj + tx;
    float sqj = g_sqt[j];
#pragma unroll
    for (int q = 0; q < 4; q++) {
        int li = ty * 4 + q, i = bi + li;
        float dot = 0.f;
#pragma unroll
        for (int d = 0; d < DIM; d++) dot += A[li][d] * B[tx][d];
        float d2 = fmaxf(g_sqx[i] + sqj - 2.f * dot, 0.f);
        g_Ks[(size_t)i * NTE2 + j] = sf2 * expf(-d2);
    }
}

// y -> column 2048 of Ks; zero the pad columns (every run, so replays stay clean)
__global__ void k_append_y(const float* __restrict__ y) {
    int idx = blockIdx.x * 256 + threadIdx.x;   // over NTR*128
    int i = idx >> 7, c = idx & 127;
    g_Ks[(size_t)i * NTE2 + NTE + c] = (c == 0) ? y[i] : 0.f;
}

// Ks -> V (bulk copy so the trsm can run in place, leaving fp32 Ks intact)
__global__ void k_copy_ks() {
    size_t idx = (size_t)blockIdx.x * 256 + threadIdx.x;   // float4 units
    ((float4*)g_V)[idx] = ((const float4*)g_Ks)[idx];
}

// ------------------- fused potrf(128) + triangular inverse (2 barriers/col)
__global__ void k_potrf_invert(int kb) {
    extern __shared__ float sh[];
    float (*S )[BS + 1] = (float (*)[BS + 1])sh;
    float (*Mi)[BS + 1] = (float (*)[BS + 1])(sh + BS * (BS + 1));
    float* colj = sh + 2 * BS * (BS + 1);
    float* srd  = colj + BS;
    const int t = threadIdx.x;        // 512
    float* src = g_L + (size_t)(kb * BS) * NTR + kb * BS;
    for (int idx = t; idx < BS * BS; idx += 512) {
        int r = idx >> 7, c = idx & 127;
        S[r][c]  = src[(size_t)r * NTR + c];
        Mi[r][c] = (r == c) ? 1.f : 0.f;
    }
    __syncthreads();
    if (t == 0) srd[0] = rsqrtf(S[0][0]);
    __syncthreads();
    const int lane = t & 31, w = t >> 5;   // 16 warps
    for (int j = 0; j < BS; j++) {
        float rd = srd[0];
        for (int i = j + t; i < BS; i += 512) { float v = S[i][j] * rd; colj[i] = v; S[i][j] = v; }
        for (int c = t; c <= j; c += 512) Mi[j][c] *= rd;
        __syncthreads();
        for (int i = j + 1 + w; i < BS; i += 16) {
            float f = colj[i];
            for (int k = j + 1 + lane; k < BS; k += 32) S[i][k] -= f * colj[k];
            for (int c = lane; c <= j; c += 32)        Mi[i][c] -= f * Mi[j][c];
            if (i == j + 1 && lane == 0) srd[0] = rsqrtf(S[i][i]);
        }
        __syncthreads();
    }
    for (int idx = t; idx < BS * BS; idx += 512) {
        int r = idx >> 7, c = idx & 127;
        if (c <= r) src[(size_t)r * NTR + c] = S[r][c];
        g_invD[kb * BS * BS + idx] = (c <= r) ? Mi[r][c] : 0.f;
    }
}

// -------------------------------------------------- tf32 helpers
__device__ __forceinline__ float tf32r(float x) {
    uint32_t u;
    asm("cvt.rna.tf32.f32 %0, %1;" : "=r"(u) : "f"(x));
    return __uint_as_float(u);
}
__device__ __forceinline__ void mma_tf32(float* d, const uint32_t* a, const uint32_t* b) {
    asm volatile(
        "mma.sync.aligned.m16n8k8.row.col.f32.tf32.tf32.f32 "
        "{%0,%1,%2,%3},{%4,%5,%6,%7},{%8,%9},{%0,%1,%2,%3};"
        : "+f"(d[0]), "+f"(d[1]), "+f"(d[2]), "+f"(d[3])
        : "r"(a[0]), "r"(a[1]), "r"(a[2]), "r"(a[3]), "r"(b[0]), "r"(b[1]));
}

// --- K=128 tensor-core GEMM (tf32 RNA), reg+smem double-buffered ---
// TB=1: B is row-major [col][k];  SUB: C -= A*B;  SYRK: lower tiles only
template <int TB, int SUB, int SYRK>
__global__ void __launch_bounds__(256, 2) k_gemm128(
    const float* __restrict__ A, int lda,
    const float* __restrict__ B, int ldb,
    float* __restrict__ C, int ldc)
{
    if (SYRK && (blockIdx.y < blockIdx.x)) return;
    const int row0 = blockIdx.y * 128;
    const int col0 = blockIdx.x * 128;
    __shared__ float As[2][16][136];
    __shared__ float Bs[2][16][136];
    const int t = threadIdx.x;
    const int lane = t & 31, wid = t >> 5;
    const int wm = wid & 3, wn = wid >> 2;          // 4 x 2 warp grid
    const int g = lane >> 2, tig = lane & 3;
    const int ra = t & 127, fa = t >> 7;            // NT-style staging
    const int kk = t >> 4, cq = t & 15;             // NN B staging

    const float* aptr   = A + (size_t)(row0 + ra) * lda + fa * 4;
    const float* bptrNT = B + (size_t)(col0 + ra) * ldb + fa * 4;
    const float* bptrNN = B + (size_t)kk * ldb + col0 + cq * 4;

    float4 rA0, rA1, rB0, rB1;
    auto ldgA = [&](int k0) {
        rA0 = *(const float4*)(aptr + k0);
        rA1 = *(const float4*)(aptr + k0 + 8);
    };
    auto ldgB = [&](int k0) {
        if (TB) {
            rB0 = *(const float4*)(bptrNT + k0);
            rB1 = *(const float4*)(bptrNT + k0 + 8);
        } else {
            rB0 = *(const float4*)(bptrNN + (size_t)k0 * ldb);
            rB1 = *(const float4*)(bptrNN + (size_t)k0 * ldb + 64);
        }
    };
    auto stsA = [&](int s) {
        As[s][fa * 4 + 0][ra] = tf32r(rA0.x); As[s][fa * 4 + 1][ra] = tf32r(rA0.y);
        As[s][fa * 4 + 2][ra] = tf32r(rA0.z); As[s][fa * 4 + 3][ra] = tf32r(rA0.w);
        As[s][8 + fa * 4 + 0][ra] = tf32r(rA1.x); As[s][8 + fa * 4 + 1][ra] = tf32r(rA1.y);
        As[s][8 + fa * 4 + 2][ra] = tf32r(rA1.z); As[s][8 + fa * 4 + 3][ra] = tf32r(rA1.w);
    };
    auto stsB = [&](int s) {
        if (TB) {
            Bs[s][fa * 4 + 0][ra] = tf32r(rB0.x); Bs[s][fa * 4 + 1][ra] = tf32r(rB0.y);
            Bs[s][fa * 4 + 2][ra] = tf32r(rB0.z); Bs[s][fa * 4 + 3][ra] = tf32r(rB0.w);
            Bs[s][8 + fa * 4 + 0][ra] = tf32r(rB1.x); Bs[s][8 + fa * 4 + 1][ra] = tf32r(rB1.y);
            Bs[s][8 + fa * 4 + 2][ra] = tf32r(rB1.z); Bs[s][8 + fa * 4 + 3][ra] = tf32r(rB1.w);
        } else {
            float4 w0 = make_float4(tf32r(rB0.x), tf32r(rB0.y), tf32r(rB0.z), tf32r(rB0.w));
            float4 w1 = make_float4(tf32r(rB1.x), tf32r(rB1.y), tf32r(rB1.z), tf32r(rB1.w));
            *(float4*)&Bs[s][kk][cq * 4]      = w0;
            *(float4*)&Bs[s][kk][64 + cq * 4] = w1;
        }
    };

    float acc[2][8][4];
#pragma unroll
    for (int i = 0; i < 2; i++)
#pragma unroll
        for (int j = 0; j < 8; j++)
#pragma unroll
            for (int q = 0; q < 4; q++) acc[i][j][q] = 0.f;

    ldgA(0); ldgB(0);
    stsA(0); stsB(0);
    __syncthreads();

#pragma unroll
    for (int k0 = 0; k0 < 8; k0++) {
        const int cur = k0 & 1;
        if (k0 < 7) { ldgA((k0 + 1) * 16); ldgB((k0 + 1) * 16); }
#pragma unroll
        for (int kf = 0; kf < 2; kf++) {
            const int kb = kf * 8;
            uint32_t a[2][4], b[8][2];
#pragma unroll
            for (int mt = 0; mt < 2; mt++) {
                int rb = wm * 32 + mt * 16;
                a[mt][0] = __float_as_uint(As[cur][kb + tig][rb + g]);
                a[mt][1] = __float_as_uint(As[cur][kb + tig][rb + g + 8]);
                a[mt][2] = __float_as_uint(As[cur][kb + tig + 4][rb + g]);
                a[mt][3] = __float_as_uint(As[cur][kb + tig + 4][rb + g + 8]);
            }
#pragma unroll
            for (int nt = 0; nt < 8; nt++) {
                int cb = wn * 64 + nt * 8;
                b[nt][0] = __float_as_uint(Bs[cur][kb + tig][cb + g]);
                b[nt][1] = __float_as_uint(Bs[cur][kb + tig + 4][cb + g]);
            }
#pragma unroll
            for (int mt = 0; mt < 2; mt++)
#pragma unroll
                for (int nt = 0; nt < 8; nt++)
                    mma_tf32(acc[mt][nt], a[mt], b[nt]);
        }
        if (k0 < 7) { stsA(cur ^ 1); stsB(cur ^ 1); }
        __syncthreads();
    }

    // ---- epilogue ----
#pragma unroll
    for (int mt = 0; mt < 2; mt++) {
        int r0 = row0 + wm * 32 + mt * 16 + g;
#pragma unroll
        for (int nt = 0; nt < 8; nt++) {
            int c = col0 + wn * 64 + nt * 8 + tig * 2;
            float2* p0 = (float2*)(C + (size_t)r0 * ldc + c);
            float2* p1 = (float2*)(C + (size_t)(r0 + 8) * ldc + c);
            if (SUB) {
                float2 v0 = *p0, v1 = *p1;
                v0.x -= acc[mt][nt][0]; v0.y -= acc[mt][nt][1];
                v1.x -= acc[mt][nt][2]; v1.y -= acc[mt][nt][3];
                *p0 = v0; *p1 = v1;
            } else {
                *p0 = make_float2(acc[mt][nt][0], acc[mt][nt][1]);
                *p1 = make_float2(acc[mt][nt][2], acc[mt][nt][3]);
            }
        }
    }
}

// ------------------------------------------ backward trsv chain (alpha = L^-T w)
__global__ void k_copy_w() {           // b = V[:, NTE] = L^{-1} y
    int i = blockIdx.x * 256 + threadIdx.x;
    if (i < NTR) g_b[i] = g_V[(size_t)i * NTE2 + NTE];
}

__global__ void k_trsv_diag_bwd(int kb) {
    __shared__ float sb[BS];
    int t = threadIdx.x;
    sb[t] = g_b[kb * BS + t];
    __syncthreads();
    const float* Mi = g_invD + kb * BS * BS;
    float s = 0.f;
#pragma unroll 4
    for (int j = 0; j < BS; j++) s += Mi[j * BS + t] * sb[j];
    g_alpha[kb * BS + t] = s;
}

__global__ void k_trsv_upd_bwd(int kb) {
    __shared__ float sx[BS];
    int t = threadIdx.x;
    if (t < BS) sx[t] = g_alpha[kb * BS + t];
    __syncthreads();
    int i = blockIdx.x * 256 + t;
    if (i >= kb * BS) return;
    float s = 0.f;
#pragma unroll 4
    for (int j = 0; j < BS; j++) s += g_L[(size_t)(kb * BS + j) * NTR + i] * sx[j];
    g_b[i] -= s;
}

// ----------------------------------------------------------- reductions
__global__ void k_part_mean() {        // fp32: mean = Ks^T alpha (Ks intact)
    __shared__ float sa[512];
    int t = threadIdx.x;               // 128
    int n0 = blockIdx.y * 512;
    for (int q = t; q < 512; q += 128) sa[q] = g_alpha[n0 + q];
    __syncthreads();
    int m = blockIdx.x * 128 + t;
    float s = 0.f;
    for (int q = 0; q < 512; q++) s += g_Ks[(size_t)(n0 + q) * NTE2 + m] * sa[q];
    g_partM[blockIdx.y * NTE + m] = s;
}

__global__ void k_part_var() {
    int t = threadIdx.x;
    int n0 = blockIdx.y * 512;
    int m = blockIdx.x * 128 + t;
    float s = 0.f;
    for (int q = 0; q < 512; q++) { float v = g_V[(size_t)(n0 + q) * NTE2 + m]; s += v * v; }
    g_partV[blockIdx.y * NTE + m] = s;
}

__global__ void k_finalize(float* out) {
    int m = blockIdx.x * 256 + threadIdx.x;
    if (m >= NTE) return;
    float sm = 0.f, sv = 0.f;
#pragma unroll
    for (int p = 0; p < 8; p++) { sm += g_partM[p * NTE + m]; sv += g_partV[p * NTE + m]; }
    out[m] = sm;
    out[NTE + m] = g_params[0] + g_params[1] - sv;
}

// ----------------------------------------------------------------- launch
extern "C" void kernel_launch(void* const* d_in, const int* in_sizes, int n_in,
                              void* d_out, int out_size)
{
    const float* train_x = (const float*)d_in[0];
    const float* train_y = (const float*)d_in[1];
    const float* test_x  = (const float*)d_in[2];
    const float* lsf2    = (const float*)d_in[3];
    const float* ll2     = (const float*)d_in[4];
    const float* lsn2    = (const float*)d_in[5];
    float* out = (float*)d_out;

    float *pL, *pKs, *pV, *pInvD, *pXs, *pTs, *pSqx, *pSqt;
    cudaGetSymbolAddress((void**)&pL,    g_L);
    cudaGetSymbolAddress((void**)&pKs,   g_Ks);
    cudaGetSymbolAddress((void**)&pV,    g_V);
    cudaGetSymbolAddress((void**)&pInvD, g_invD);
    cudaGetSymbolAddress((void**)&pXs,   g_xs);
    cudaGetSymbolAddress((void**)&pTs,   g_ts);
    cudaGetSymbolAddress((void**)&pSqx,  g_sqx);
    cudaGetSymbolAddress((void**)&pSqt,  g_sqt);

    const size_t smem_pi = (2 * BS * (BS + 1) + BS + 32) * sizeof(float);
    cudaFuncSetAttribute(k_potrf_invert, cudaFuncAttributeMaxDynamicSharedMemorySize,
                         (int)smem_pi);

    k_prep<<<1, 32>>>(lsf2, ll2, lsn2);
    k_scale<<<(NTR + 255) / 256, 256>>>(train_x, pXs, pSqx, NTR);
    k_scale<<<(NTE + 255) / 256, 256>>>(test_x,  pTs, pSqt, NTE);
    k_build_knn<<<dim3(NTR / 32, NTR / 32), 256>>>();
    k_build_ks <<<dim3(NTE / 32, NTR / 32), 256>>>();
    k_append_y <<<NTR * 128 / 256, 256>>>(train_y);
    k_copy_ks  <<<(NTR * NTE2 / 4) / 256, 256>>>();

    // ---- blocked Cholesky (right-looking); panel trsm in place ----
    for (int kb = 0; kb < NB; kb++) {
        k_potrf_invert<<<1, 512, smem_pi>>>(kb);
        int R = NTR - (kb + 1) * BS;
        if (R > 0) {
            float* panel = pL + (size_t)(kb + 1) * BS * NTR + (size_t)kb * BS;
            k_gemm128<1, 0, 0><<<dim3(1, R / BS), 256>>>(
                panel, NTR, pInvD + kb * BS * BS, BS, panel, NTR);
            float* C22 = pL + (size_t)(kb + 1) * BS * (NTR + 1);
            k_gemm128<1, 1, 1><<<dim3(R / BS, R / BS), 256>>>(
                panel, NTR, panel, NTR, C22, NTR);
        }
    }

    // ---- V = L^{-1} [Kstar | y]  (in place in g_V; g_Ks stays intact) ----
    for (int kb = 0; kb < NB; kb++) {
        float* vkb = pV + (size_t)kb * BS * NTE2;
        k_gemm128<0, 0, 0><<<dim3(NTE2 / 128, 1), 256>>>(
            pInvD + kb * BS * BS, BS, vkb, NTE2, vkb, NTE2);
        int R = NTR - (kb + 1) * BS;
        if (R > 0) {
            k_gemm128<0, 1, 0><<<dim3(NTE2 / 128, R / BS), 256>>>(
                pL + (size_t)(kb + 1) * BS * NTR + (size_t)kb * BS, NTR,
                vkb, NTE2,
                pV + (size_t)(kb + 1) * BS * NTE2, NTE2);
        }
    }

    // ---- alpha = L^{-T} w (backward chain; w = V[:,2048]) ----
    k_copy_w<<<(NTR + 255) / 256, 256>>>();
    for (int kb = NB - 1; kb >= 0; kb--) {
        k_trsv_diag_bwd<<<1, BS>>>(kb);
        if (kb > 0) k_trsv_upd_bwd<<<(kb * BS + 255) / 256, 256>>>(kb);
    }

    // ---- outputs ----
    k_part_mean<<<dim3(NTE / 128, 8), 128>>>();
    k_part_var <<<dim3(NTE / 128, 8), 128>>>();
    k_finalize <<<(NTE + 255) / 256, 256>>>(out);
}

// round 5
// speedup vs baseline: 1.0510x; 1.0510x over previous
#include <cuda_runtime.h>
#include <cstdint>

constexpr int NTR  = 4096;
constexpr int NTE  = 2048;
constexpr int NTE2 = 2176;          // NTE + 128 (y folded in as col 2048)
constexpr int DIM  = 16;
constexpr int BS   = 128;
constexpr int NB   = NTR / BS;      // 32

// ---- scratch (device globals; no runtime allocation) ----
__device__ float g_L [(size_t)NTR * NTR];    // Knn -> L (lower)
__device__ float g_Ks[(size_t)NTR * NTE2];   // [Kstar | y | 0-pad]  (stays intact)
__device__ float g_V [(size_t)NTR * NTE2];   // copy of Ks, solved in place -> V
__device__ float g_invD[NB * BS * BS];       // inverses of diag L blocks (RNA-rounded)
__device__ float g_xs[NTR * DIM];
__device__ float g_ts[NTE * DIM];
__device__ float g_sqx[NTR];
__device__ float g_sqt[NTE];
__device__ float g_b[NTR];
__device__ float g_alpha[NTR];
__device__ float g_partM[8 * NTE];
__device__ float g_partV[8 * NTE];
__device__ float g_params[2];                // sigmaf2, sigman2
__device__ float g_scale[DIM];

// -------------------------------------------------- tf32 helpers
__device__ __forceinline__ float tf32r(float x) {
    uint32_t u;
    asm("cvt.rna.tf32.f32 %0, %1;" : "=r"(u) : "f"(x));
    return __uint_as_float(u);
}
__device__ __forceinline__ void mma_tf32(float* d, const uint32_t* a, const uint32_t* b) {
    asm volatile(
        "mma.sync.aligned.m16n8k8.row.col.f32.tf32.tf32.f32 "
        "{%0,%1,%2,%3},{%4,%5,%6,%7},{%8,%9},{%0,%1,%2,%3};"
        : "+f"(d[0]), "+f"(d[1]), "+f"(d[2]), "+f"(d[3])
        : "r"(a[0]), "r"(a[1]), "r"(a[2]), "r"(a[3]), "r"(b[0]), "r"(b[1]));
}
__device__ __forceinline__ void cpa16(uint32_t dst, const void* src) {
    asm volatile("cp.async.cg.shared.global [%0], [%1], 16;\n" :: "r"(dst), "l"(src));
}
__device__ __forceinline__ void cpa_commit() {
    asm volatile("cp.async.commit_group;\n");
}

// ---------------------------------------------------------------- prep
__global__ void k_prep(const float* lsf2, const float* ll2, const float* lsn2) {
    int t = threadIdx.x;
    if (t == 0) { g_params[0] = expf(lsf2[0]); g_params[1] = expf(lsn2[0]); }
    if (t < DIM) g_scale[t] = sqrtf(0.5f * expf(-ll2[t]));
}

__global__ void k_scale(const float* __restrict__ in, float* __restrict__ out,
                        float* __restrict__ sq, int n) {
    int i = blockIdx.x * blockDim.x + threadIdx.x;
    if (i >= n) return;
    float s = 0.f;
#pragma unroll
    for (int d = 0; d < DIM; d++) {
        float v = in[i * DIM + d] * g_scale[d];
        out[i * DIM + d] = v;
        s += v * v;
    }
    sq[i] = s;
}

// ------------------------------------------------------- kernel builders
__global__ void k_build_knn() {
    __shared__ float A[32][DIM];
    __shared__ float B[32][DIM + 1];
    int bi = blockIdx.y * 32, bj = blockIdx.x * 32;
    int t = threadIdx.x;
    for (int idx = t; idx < 32 * DIM; idx += 256) {
        int r = idx / DIM, d = idx % DIM;
        A[r][d] = g_xs[(bi + r) * DIM + d];
        B[r][d] = g_xs[(bj + r) * DIM + d];
    }
    __syncthreads();
    float sf2 = g_params[0], sn2 = g_params[1];
    int tx = t & 31, ty = t >> 5;
    int j = bj + tx;
    float sqj = g_sqx[j];
#pragma unroll
    for (int q = 0; q < 4; q++) {
        int li = ty * 4 + q, i = bi + li;
        float dot = 0.f;
#pragma unroll
        for (int d = 0; d < DIM; d++) dot += A[li][d] * B[tx][d];
        float d2 = fmaxf(g_sqx[i] + sqj - 2.f * dot, 0.f);
        float v = sf2 * expf(-d2);
        if (i == j) v += sn2;
        g_L[(size_t)i * NTR + j] = v;
    }
}

__global__ void k_build_ks() {
    __shared__ float A[32][DIM];
    __shared__ float B[32][DIM + 1];
    int bi = blockIdx.y * 32, bj = blockIdx.x * 32;
    int t = threadIdx.x;
    for (int idx = t; idx < 32 * DIM; idx += 256) {
        int r = idx / DIM, d = idx % DIM;
        A[r][d] = g_xs[(bi + r) * DIM + d];
        B[r][d] = g_ts[(bj + r) * DIM + d];
    }
    __syncthreads();
    float sf2 = g_params[0];
    int tx = t & 31, ty = t >> 5;
    int j = bj + tx;
    float sqj = g_sqt[j];
#pragma unroll
    for (int q = 0; q < 4; q++) {
        int li = ty * 4 + q, i = bi + li;
        float dot = 0.f;
#pragma unroll
        for (int d = 0; d < DIM; d++) dot += A[li][d] * B[tx][d];
        float d2 = fmaxf(g_sqx[i] + sqj - 2.f * dot, 0.f);
        g_Ks[(size_t)i * NTE2 + j] = sf2 * expf(-d2);
    }
}

// y -> column 2048 of Ks; zero the pad columns
__global__ void k_append_y(const float* __restrict__ y) {
    int idx = blockIdx.x * 256 + threadIdx.x;   // over NTR*128
    int i = idx >> 7, c = idx & 127;
    g_Ks[(size_t)i * NTE2 + NTE + c] = (c == 0) ? y[i] : 0.f;
}

// Ks -> V (bulk copy so the trsm can run in place, leaving fp32 Ks intact)
__global__ void k_copy_ks() {
    size_t idx = (size_t)blockIdx.x * 256 + threadIdx.x;   // float4 units
    ((float4*)g_V)[idx] = ((const float4*)g_Ks)[idx];
}

// ------------------- fused potrf(128) + triangular inverse (2 barriers/col)
__global__ void k_potrf_invert(int kb) {
    extern __shared__ float sh[];
    float (*S )[BS + 1] = (float (*)[BS + 1])sh;
    float (*Mi)[BS + 1] = (float (*)[BS + 1])(sh + BS * (BS + 1));
    float* colj = sh + 2 * BS * (BS + 1);
    float* srd  = colj + BS;
    const int t = threadIdx.x;        // 512
    float* src = g_L + (size_t)(kb * BS) * NTR + kb * BS;
    for (int idx = t; idx < BS * BS; idx += 512) {
        int r = idx >> 7, c = idx & 127;
        S[r][c]  = src[(size_t)r * NTR + c];
        Mi[r][c] = (r == c) ? 1.f : 0.f;
    }
    __syncthreads();
    if (t == 0) srd[0] = rsqrtf(S[0][0]);
    __syncthreads();
    const int lane = t & 31, w = t >> 5;   // 16 warps
    for (int j = 0; j < BS; j++) {
        float rd = srd[0];
        for (int i = j + t; i < BS; i += 512) { float v = S[i][j] * rd; colj[i] = v; S[i][j] = v; }
        for (int c = t; c <= j; c += 512) Mi[j][c] *= rd;
        __syncthreads();
        for (int i = j + 1 + w; i < BS; i += 16) {
            float f = colj[i];
            for (int k = j + 1 + lane; k < BS; k += 32) S[i][k] -= f * colj[k];
            for (int c = lane; c <= j; c += 32)        Mi[i][c] -= f * Mi[j][c];
            if (i == j + 1 && lane == 0) srd[0] = rsqrtf(S[i][i]);
        }
        __syncthreads();
    }
    for (int idx = t; idx < BS * BS; idx += 512) {
        int r = idx >> 7, c = idx & 127;
        if (c <= r) src[(size_t)r * NTR + c] = S[r][c];
        g_invD[kb * BS * BS + idx] = (c <= r) ? tf32r(Mi[r][c]) : 0.f;  // input-grade
    }
}

// ================= FAST GEMM: cp.async 3-stage pipeline, raw tf32 inputs =====
// Inputs MUST already be RNA-rounded (producers guarantee this).
// C -= A * op(B).  TB=1: B row-major [col][k];  SYRK: lower tiles only.
// smem: A [3][128][20], B: TB? [3][128][20] : [3][16][136]
template <int TB, int SYRK>
__global__ void __launch_bounds__(256, 2) k_gemm_async(
    const float* __restrict__ A, int lda,
    const float* __restrict__ B, int ldb,
    float* __restrict__ C, int ldc)
{
    if (SYRK && (blockIdx.y < blockIdx.x)) return;
    extern __shared__ float sm[];
    constexpr int ASTG = 128 * 20;                    // floats per A stage
    constexpr int BSTG = TB ? 128 * 20 : 16 * 136;    // floats per B stage
    float* Ab = sm;
    float* Bb = sm + 3 * ASTG;

    const int row0 = blockIdx.y * 128;
    const int col0 = blockIdx.x * 128;
    const int t = threadIdx.x;
    const int lane = t & 31, wid = t >> 5;
    const int wm = wid & 3, wn = wid >> 2;            // 4 x 2 warp grid
    const int g = lane >> 2, tig = lane & 3;

    const uint32_t smbase = (uint32_t)__cvta_generic_to_shared(sm);

    // staging indices
    const int arow = t & 127, acp = t >> 7;           // A (and NT-B): row, chunk-pair
    const int bkk = t >> 4, bcq = t & 15;             // NN-B

    auto issue = [&](int s, int stg) {                // slice s -> stage stg
        const int k0 = s * 16;
        {
            const float* src = A + (size_t)(row0 + arow) * lda + k0 + acp * 8;
            uint32_t dst = smbase + (uint32_t)(stg * ASTG + arow * 20 + acp * 8) * 4u;
            cpa16(dst, src);
            cpa16(dst + 16, src + 4);
        }
        if (TB) {
            const float* src = B + (size_t)(col0 + arow) * ldb + k0 + acp * 8;
            uint32_t dst = smbase + (uint32_t)(3 * ASTG + stg * BSTG + arow * 20 + acp * 8) * 4u;
            cpa16(dst, src);
            cpa16(dst + 16, src + 4);
        } else {
            const float* src = B + (size_t)(k0 + bkk) * ldb + col0 + bcq * 4;
            uint32_t dst = smbase + (uint32_t)(3 * ASTG + stg * BSTG + bkk * 136 + bcq * 4) * 4u;
            cpa16(dst, src);
            cpa16(dst + 256, src + 64);
        }
        cpa_commit();
    };

    float acc[2][8][4];
#pragma unroll
    for (int i = 0; i < 2; i++)
#pragma unroll
        for (int j = 0; j < 8; j++)
#pragma unroll
            for (int q = 0; q < 4; q++) acc[i][j][q] = 0.f;

    issue(0, 0);
    issue(1, 1);

#pragma unroll
    for (int s = 0; s < 8; s++) {
        if (s < 7) asm volatile("cp.async.wait_group 1;\n");
        else       asm volatile("cp.async.wait_group 0;\n");
        __syncthreads();
        if (s + 2 < 8) issue(s + 2, (s + 2) % 3);

        const float* Asb = Ab + (s % 3) * ASTG;
        const float* Bsb = Bb + (s % 3) * BSTG;
#pragma unroll
        for (int kf = 0; kf < 2; kf++) {
            const int kb = kf * 8;
            uint32_t a[2][4], b[8][2];
#pragma unroll
            for (int mt = 0; mt < 2; mt++) {
                int rb = wm * 32 + mt * 16 + g;
                a[mt][0] = __float_as_uint(Asb[rb * 20 + kb + tig]);
                a[mt][1] = __float_as_uint(Asb[(rb + 8) * 20 + kb + tig]);
                a[mt][2] = __float_as_uint(Asb[rb * 20 + kb + tig + 4]);
                a[mt][3] = __float_as_uint(Asb[(rb + 8) * 20 + kb + tig + 4]);
            }
#pragma unroll
            for (int nt = 0; nt < 8; nt++) {
                int cb = wn * 64 + nt * 8 + g;
                if (TB) {
                    b[nt][0] = __float_as_uint(Bsb[cb * 20 + kb + tig]);
                    b[nt][1] = __float_as_uint(Bsb[cb * 20 + kb + tig + 4]);
                } else {
                    b[nt][0] = __float_as_uint(Bsb[(kb + tig) * 136 + cb]);
                    b[nt][1] = __float_as_uint(Bsb[(kb + tig + 4) * 136 + cb]);
                }
            }
#pragma unroll
            for (int mt = 0; mt < 2; mt++)
#pragma unroll
                for (int nt = 0; nt < 8; nt++)
                    mma_tf32(acc[mt][nt], a[mt], b[nt]);
        }
        __syncthreads();
    }

    // ---- epilogue: C -= acc (fp32 accumulate, no rounding) ----
#pragma unroll
    for (int mt = 0; mt < 2; mt++) {
        int r0 = row0 + wm * 32 + mt * 16 + g;
#pragma unroll
        for (int nt = 0; nt < 8; nt++) {
            int c = col0 + wn * 64 + nt * 8 + tig * 2;
            float2* p0 = (float2*)(C + (size_t)r0 * ldc + c);
            float2* p1 = (float2*)(C + (size_t)(r0 + 8) * ldc + c);
            float2 v0 = *p0, v1 = *p1;
            v0.x -= acc[mt][nt][0]; v0.y -= acc[mt][nt][1];
            v1.x -= acc[mt][nt][2]; v1.y -= acc[mt][nt][3];
            *p0 = v0; *p1 = v1;
        }
    }
}

// ============ CVT GEMM (round-2 style): C = round_rna(A * op(B)) ============
// Used where inputs are raw fp32 accumulators (panel trsm, diag apply).
// Inputs RNA-rounded during staging; output RNA-rounded (input-grade).
template <int TB>
__global__ void __launch_bounds__(256, 2) k_gemm_cvt(
    const float* __restrict__ A, int lda,
    const float* __restrict__ B, int ldb,
    float* __restrict__ C, int ldc)
{
    const int row0 = blockIdx.y * 128;
    const int col0 = blockIdx.x * 128;
    __shared__ float As[16][136];
    __shared__ float Bs[16][136];
    const int t = threadIdx.x;
    const int lane = t & 31, wid = t >> 5;
    const int wm = wid & 3, wn = wid >> 2;
    const int g = lane >> 2, tig = lane & 3;
    const int ra = t & 127, fa = t >> 7;
    const int kk = t >> 4, cq = t & 15;

    float acc[2][8][4];
#pragma unroll
    for (int i = 0; i < 2; i++)
#pragma unroll
        for (int j = 0; j < 8; j++)
#pragma unroll
            for (int q = 0; q < 4; q++) acc[i][j][q] = 0.f;

    for (int k0 = 0; k0 < 128; k0 += 16) {
        {
            const float* ap = A + (size_t)(row0 + ra) * lda + k0 + fa * 4;
            float4 v0 = *(const float4*)ap;
            float4 v1 = *(const float4*)(ap + 8);
            As[fa * 4 + 0][ra] = tf32r(v0.x); As[fa * 4 + 1][ra] = tf32r(v0.y);
            As[fa * 4 + 2][ra] = tf32r(v0.z); As[fa * 4 + 3][ra] = tf32r(v0.w);
            As[8 + fa * 4 + 0][ra] = tf32r(v1.x); As[8 + fa * 4 + 1][ra] = tf32r(v1.y);
            As[8 + fa * 4 + 2][ra] = tf32r(v1.z); As[8 + fa * 4 + 3][ra] = tf32r(v1.w);
        }
        if (TB) {
            const float* bp = B + (size_t)(col0 + ra) * ldb + k0 + fa * 4;
            float4 v0 = *(const float4*)bp;
            float4 v1 = *(const float4*)(bp + 8);
            Bs[fa * 4 + 0][ra] = tf32r(v0.x); Bs[fa * 4 + 1][ra] = tf32r(v0.y);
            Bs[fa * 4 + 2][ra] = tf32r(v0.z); Bs[fa * 4 + 3][ra] = tf32r(v0.w);
            Bs[8 + fa * 4 + 0][ra] = tf32r(v1.x); Bs[8 + fa * 4 + 1][ra] = tf32r(v1.y);
            Bs[8 + fa * 4 + 2][ra] = tf32r(v1.z); Bs[8 + fa * 4 + 3][ra] = tf32r(v1.w);
        } else {
            const float* bp = B + (size_t)(k0 + kk) * ldb + col0 + cq * 4;
            float4 v0 = *(const float4*)bp;
            float4 v1 = *(const float4*)(bp + 64);
            float4 w0 = make_float4(tf32r(v0.x), tf32r(v0.y), tf32r(v0.z), tf32r(v0.w));
            float4 w1 = make_float4(tf32r(v1.x), tf32r(v1.y), tf32r(v1.z), tf32r(v1.w));
            *(float4*)&Bs[kk][cq * 4]      = w0;
            *(float4*)&Bs[kk][64 + cq * 4] = w1;
        }
        __syncthreads();
#pragma unroll
        for (int kf = 0; kf < 2; kf++) {
            const int kb = kf * 8;
            uint32_t a[2][4], b[8][2];
#pragma unroll
            for (int mt = 0; mt < 2; mt++) {
                int rb = wm * 32 + mt * 16;
                a[mt][0] = __float_as_uint(As[kb + tig][rb + g]);
                a[mt][1] = __float_as_uint(As[kb + tig][rb + g + 8]);
                a[mt][2] = __float_as_uint(As[kb + tig + 4][rb + g]);
                a[mt][3] = __float_as_uint(As[kb + tig + 4][rb + g + 8]);
            }
#pragma unroll
            for (int nt = 0; nt < 8; nt++) {
                int cb = wn * 64 + nt * 8;
                b[nt][0] = __float_as_uint(Bs[kb + tig][cb + g]);
                b[nt][1] = __float_as_uint(Bs[kb + tig + 4][cb + g]);
            }
#pragma unroll
            for (int mt = 0; mt < 2; mt++)
#pragma unroll
                for (int nt = 0; nt < 8; nt++)
                    mma_tf32(acc[mt][nt], a[mt], b[nt]);
        }
        __syncthreads();
    }

    // ---- epilogue: write RNA-rounded (input-grade) ----
#pragma unroll
    for (int mt = 0; mt < 2; mt++) {
        int r0 = row0 + wm * 32 + mt * 16 + g;
#pragma unroll
        for (int nt = 0; nt < 8; nt++) {
            int c = col0 + wn * 64 + nt * 8 + tig * 2;
            float2* p0 = (float2*)(C + (size_t)r0 * ldc + c);
            float2* p1 = (float2*)(C + (size_t)(r0 + 8) * ldc + c);
            *p0 = make_float2(tf32r(acc[mt][nt][0]), tf32r(acc[mt][nt][1]));
            *p1 = make_float2(tf32r(acc[mt][nt][2]), tf32r(acc[mt][nt][3]));
        }
    }
}

// ------------------------------------------ backward trsv chain (alpha = L^-T w)
__global__ void k_copy_w() {           // b = V[:, NTE] = L^{-1} y
    int i = blockIdx.x * 256 + threadIdx.x;
    if (i < NTR) g_b[i] = g_V[(size_t)i * NTE2 + NTE];
}

__global__ void k_trsv_diag_bwd(int kb) {
    __shared__ float sb[BS];
    int t = threadIdx.x;
    sb[t] = g_b[kb * BS + t];
    __syncthreads();
    const float* Mi = g_invD + kb * BS * BS;
    float s = 0.f;
#pragma unroll 4
    for (int j = 0; j < BS; j++) s += Mi[j * BS + t] * sb[j];
    g_alpha[kb * BS + t] = s;
}

__global__ void k_trsv_upd_bwd(int kb) {
    __shared__ float sx[BS];
    int t = threadIdx.x;
    if (t < BS) sx[t] = g_alpha[kb * BS + t];
    __syncthreads();
    int i = blockIdx.x * 256 + t;
    if (i >= kb * BS) return;
    float s = 0.f;
#pragma unroll 4
    for (int j = 0; j < BS; j++) s += g_L[(size_t)(kb * BS + j) * NTR + i] * sx[j];
    g_b[i] -= s;
}

// ----------------------------------------------------------- reductions
__global__ void k_part_mean() {        // fp32: mean = Ks^T alpha (Ks intact)
    __shared__ float sa[512];
    int t = threadIdx.x;               // 128
    int n0 = blockIdx.y * 512;
    for (int q = t; q < 512; q += 128) sa[q] = g_alpha[n0 + q];
    __syncthreads();
    int m = blockIdx.x * 128 + t;
    float s = 0.f;
    for (int q = 0; q < 512; q++) s += g_Ks[(size_t)(n0 + q) * NTE2 + m] * sa[q];
    g_partM[blockIdx.y * NTE + m] = s;
}

__global__ void k_part_var() {
    int t = threadIdx.x;
    int n0 = blockIdx.y * 512;
    int m = blockIdx.x * 128 + t;
    float s = 0.f;
    for (int q = 0; q < 512; q++) { float v = g_V[(size_t)(n0 + q) * NTE2 + m]; s += v * v; }
    g_partV[blockIdx.y * NTE + m] = s;
}

__global__ void k_finalize(float* out) {
    int m = blockIdx.x * 256 + threadIdx.x;
    if (m >= NTE) return;
    float sm = 0.f, sv = 0.f;
#pragma unroll
    for (int p = 0; p < 8; p++) { sm += g_partM[p * NTE + m]; sv += g_partV[p * NTE + m]; }
    out[m] = sm;
    out[NTE + m] = g_params[0] + g_params[1] - sv;
}

// ----------------------------------------------------------------- launch
extern "C" void kernel_launch(void* const* d_in, const int* in_sizes, int n_in,
                              void* d_out, int out_size)
{
    const float* train_x = (const float*)d_in[0];
    const float* train_y = (const float*)d_in[1];
    const float* test_x  = (const float*)d_in[2];
    const float* lsf2    = (const float*)d_in[3];
    const float* ll2     = (const float*)d_in[4];
    const float* lsn2    = (const float*)d_in[5];
    float* out = (float*)d_out;

    float *pL, *pKs, *pV, *pInvD, *pXs, *pTs, *pSqx, *pSqt;
    cudaGetSymbolAddress((void**)&pL,    g_L);
    cudaGetSymbolAddress((void**)&pKs,   g_Ks);
    cudaGetSymbolAddress((void**)&pV,    g_V);
    cudaGetSymbolAddress((void**)&pInvD, g_invD);
    cudaGetSymbolAddress((void**)&pXs,   g_xs);
    cudaGetSymbolAddress((void**)&pTs,   g_ts);
    cudaGetSymbolAddress((void**)&pSqx,  g_sqx);
    cudaGetSymbolAddress((void**)&pSqt,  g_sqt);

    const size_t smem_pi = (2 * BS * (BS + 1) + BS + 32) * sizeof(float);
    cudaFuncSetAttribute(k_potrf_invert, cudaFuncAttributeMaxDynamicSharedMemorySize,
                         (int)smem_pi);
    const int smem_syrk = 3 * (128 * 20 + 128 * 20) * sizeof(float);   // 61440
    const int smem_vupd = 3 * (128 * 20 + 16 * 136) * sizeof(float);   // 56832
    cudaFuncSetAttribute((const void*)k_gemm_async<1, 1>,
                         cudaFuncAttributeMaxDynamicSharedMemorySize, smem_syrk);
    cudaFuncSetAttribute((const void*)k_gemm_async<0, 0>,
                         cudaFuncAttributeMaxDynamicSharedMemorySize, smem_vupd);

    k_prep<<<1, 32>>>(lsf2, ll2, lsn2);
    k_scale<<<(NTR + 255) / 256, 256>>>(train_x, pXs, pSqx, NTR);
    k_scale<<<(NTE + 255) / 256, 256>>>(test_x,  pTs, pSqt, NTE);
    k_build_knn<<<dim3(NTR / 32, NTR / 32), 256>>>();
    k_build_ks <<<dim3(NTE / 32, NTR / 32), 256>>>();
    k_append_y <<<NTR * 128 / 256, 256>>>(train_y);
    k_copy_ks  <<<(NTR * NTE2 / 4) / 256, 256>>>();

    // ---- blocked Cholesky (right-looking); panel trsm in place ----
    for (int kb = 0; kb < NB; kb++) {
        k_potrf_invert<<<1, 512, smem_pi>>>(kb);
        int R = NTR - (kb + 1) * BS;
        if (R > 0) {
            float* panel = pL + (size_t)(kb + 1) * BS * NTR + (size_t)kb * BS;
            // L21 = rna(A21) * invD^T  -> rounded output (input-grade)
            k_gemm_cvt<1><<<dim3(1, R / BS), 256>>>(
                panel, NTR, pInvD + kb * BS * BS, BS, panel, NTR);
            // A22 -= L21 * L21^T  (raw async path; inputs already rounded)
            float* C22 = pL + (size_t)(kb + 1) * BS * (NTR + 1);
            k_gemm_async<1, 1><<<dim3(R / BS, R / BS), 256, smem_syrk>>>(
                panel, NTR, panel, NTR, C22, NTR);
        }
    }

    // ---- V = L^{-1} [Kstar | y]  (in place in g_V; g_Ks stays intact) ----
    for (int kb = 0; kb < NB; kb++) {
        float* vkb = pV + (size_t)kb * BS * NTE2;
        // diag apply: V_kb = rna(invD * rna(acc)) -> rounded output
        k_gemm_cvt<0><<<dim3(NTE2 / 128, 1), 256>>>(
            pInvD + kb * BS * BS, BS, vkb, NTE2, vkb, NTE2);
        int R = NTR - (kb + 1) * BS;
        if (R > 0) {
            k_gemm_async<0, 0><<<dim3(NTE2 / 128, R / BS), 256, smem_vupd>>>(
                pL + (size_t)(kb + 1) * BS * NTR + (size_t)kb * BS, NTR,
                vkb, NTE2,
                pV + (size_t)(kb + 1) * BS * NTE2, NTE2);
        }
    }

    // ---- alpha = L^{-T} w (backward chain; w = V[:,2048]) ----
    k_copy_w<<<(NTR + 255) / 256, 256>>>();
    for (int kb = NB - 1; kb >= 0; kb--) {
        k_trsv_diag_bwd<<<1, BS>>>(kb);
        if (kb > 0) k_trsv_upd_bwd<<<(kb * BS + 255) / 256, 256>>>(kb);
    }

    // ---- outputs ----
    k_part_mean<<<dim3(NTE / 128, 8), 128>>>();
    k_part_var <<<dim3(NTE / 128, 8), 128>>>();
    k_finalize <<<(NTE + 255) / 256, 256>>>(out);
}